// round 1
// baseline (speedup 1.0000x reference)
#include <cuda_runtime.h>
#include <math.h>

#define L 4096
#define D 256
#define H 8
#define DH 32
#define FF 1024
#define WIN 128
#define TD 768   // 3*D

// ---------------- scratch (allocation-free: __device__ globals) ----------------
__device__ float g_h  [L * D];    // LN1 output
__device__ float g_qkv[L * TD];   // QKV projection
__device__ float g_o  [L * D];    // attention output (heads re-interleaved)
__device__ float g_x1 [L * D];    // x + out_proj(o)
__device__ float g_h2 [L * D];    // LN2 output
__device__ float g_f1 [L * FF];   // gelu(h2 @ w1^T + b1)

// ---------------- LayerNorm: one warp per row of 256 ----------------
__global__ void ln_kernel(const float* __restrict__ x, const float* __restrict__ gw,
                          const float* __restrict__ bw, float* __restrict__ y) {
    int row  = (blockIdx.x * blockDim.x + threadIdx.x) >> 5;
    int lane = threadIdx.x & 31;
    if (row >= L) return;
    const float* xr = x + (size_t)row * D;
    float v[8];
    float s = 0.f;
#pragma unroll
    for (int i = 0; i < 8; i++) { v[i] = xr[lane + i * 32]; s += v[i]; }
#pragma unroll
    for (int o = 16; o; o >>= 1) s += __shfl_xor_sync(0xffffffffu, s, o);
    float mu = s * (1.0f / D);
    float vs = 0.f;
#pragma unroll
    for (int i = 0; i < 8; i++) { float d = v[i] - mu; vs += d * d; }
#pragma unroll
    for (int o = 16; o; o >>= 1) vs += __shfl_xor_sync(0xffffffffu, vs, o);
    float inv = rsqrtf(vs * (1.0f / D) + 1e-5f);
    float* yr = y + (size_t)row * D;
#pragma unroll
    for (int i = 0; i < 8; i++) {
        int c = lane + i * 32;
        yr[c] = (v[i] - mu) * inv * gw[c] + bw[c];
    }
}

// ---------------- SGEMM: C[M,N] = A[M,K] @ W[N,K]^T (+bias, +gelu, +resid) ----------------
// EPI: 0 = +bias, 1 = +bias then exact GELU, 2 = +bias +resid
#define BM 128
#define BN 128
#define BK 16

template <int EPI>
__global__ __launch_bounds__(256)
void gemm_kernel(const float* __restrict__ A, const float* __restrict__ W,
                 const float* __restrict__ bias, const float* __restrict__ resid,
                 float* __restrict__ C, int M, int N, int K) {
    __shared__ float As[BK][BM];
    __shared__ float Ws[BK][BN];
    int tid = threadIdx.x;
    int tx = tid & 15, ty = tid >> 4;
    int m0 = blockIdx.y * BM, n0 = blockIdx.x * BN;

    float acc[8][8];
#pragma unroll
    for (int i = 0; i < 8; i++)
#pragma unroll
        for (int j = 0; j < 8; j++) acc[i][j] = 0.f;

    for (int k0 = 0; k0 < K; k0 += BK) {
#pragma unroll
        for (int i = 0; i < 2; i++) {
            int v = tid + i * 256;            // 0..511
            int row = v >> 2, kq = (v & 3) * 4;
            float4 f = *(const float4*)(A + (size_t)(m0 + row) * K + k0 + kq);
            As[kq + 0][row] = f.x; As[kq + 1][row] = f.y;
            As[kq + 2][row] = f.z; As[kq + 3][row] = f.w;
            f = *(const float4*)(W + (size_t)(n0 + row) * K + k0 + kq);
            Ws[kq + 0][row] = f.x; Ws[kq + 1][row] = f.y;
            Ws[kq + 2][row] = f.z; Ws[kq + 3][row] = f.w;
        }
        __syncthreads();
#pragma unroll
        for (int kk = 0; kk < BK; kk++) {
            float4 a0 = *(const float4*)&As[kk][ty * 4];
            float4 a1 = *(const float4*)&As[kk][64 + ty * 4];
            float4 b0 = *(const float4*)&Ws[kk][tx * 4];
            float4 b1 = *(const float4*)&Ws[kk][64 + tx * 4];
            float a[8] = {a0.x, a0.y, a0.z, a0.w, a1.x, a1.y, a1.z, a1.w};
            float b[8] = {b0.x, b0.y, b0.z, b0.w, b1.x, b1.y, b1.z, b1.w};
#pragma unroll
            for (int i = 0; i < 8; i++)
#pragma unroll
                for (int j = 0; j < 8; j++)
                    acc[i][j] = fmaf(a[i], b[j], acc[i][j]);
        }
        __syncthreads();
    }

#pragma unroll
    for (int i = 0; i < 8; i++) {
        int r = m0 + ((i < 4) ? (ty * 4 + i) : (64 + ty * 4 + i - 4));
#pragma unroll
        for (int j = 0; j < 8; j++) {
            int cl = n0 + ((j < 4) ? (tx * 4 + j) : (64 + tx * 4 + j - 4));
            float v = acc[i][j] + bias[cl];
            if (EPI == 1) v = 0.5f * v * (1.0f + erff(v * 0.70710678118654752f));
            if (EPI == 2) v += resid[(size_t)r * N + cl];
            C[(size_t)r * N + cl] = v;
        }
    }
}

// ---------------- Local-window attention ----------------
// Block = (head, 64-query tile). K/V window (320 keys x 32 dims) staged in smem
// with stride 33 so the dot-product reads are bank-conflict-free.
#define QT 64
#define WSLOTS (QT + 2 * WIN)   // 320
#define KVS 33                  // padded row stride

__global__ __launch_bounds__(256)
void attn_kernel(const float* __restrict__ qkv, float* __restrict__ o) {
    extern __shared__ float smem[];
    float* Ksm = smem;                       // [WSLOTS][KVS]
    float* Vsm = Ksm + WSLOTS * KVS;         // [WSLOTS][KVS]
    float* Psm = Vsm + WSLOTS * KVS;         // [8][WSLOTS]
    float* Qsm = Psm + 8 * WSLOTS;           // [8][DH]

    int h = blockIdx.y;
    int q0 = blockIdx.x * QT;
    int kstart = q0 - WIN;
    int tid = threadIdx.x;

    for (int idx = tid; idx < WSLOTS * 8; idx += 256) {
        int row = idx >> 3, f4 = (idx & 7) * 4;
        int g = kstart + row;
        float4 kv = make_float4(0.f, 0.f, 0.f, 0.f), vv = kv;
        if (g >= 0 && g < L) {
            kv = *(const float4*)(qkv + (size_t)g * TD + D     + h * DH + f4);
            vv = *(const float4*)(qkv + (size_t)g * TD + 2 * D + h * DH + f4);
        }
        float* kd = Ksm + row * KVS + f4;
        kd[0] = kv.x; kd[1] = kv.y; kd[2] = kv.z; kd[3] = kv.w;
        float* vd = Vsm + row * KVS + f4;
        vd[0] = vv.x; vd[1] = vv.y; vd[2] = vv.z; vd[3] = vv.w;
    }
    __syncthreads();

    int warp = tid >> 5, lane = tid & 31;
    const float scale = 0.17677669529663687f;  // 1/sqrt(32)

    for (int qi = warp; qi < QT; qi += 8) {
        int q = q0 + qi;
        Qsm[warp * DH + lane] = qkv[(size_t)q * TD + h * DH + lane];
        __syncwarp();

        float sreg[WSLOTS / 32];
        float mx = -1e30f;
#pragma unroll
        for (int c2 = 0; c2 < WSLOTS / 32; c2++) {
            int li = c2 * 32 + lane;
            int g = kstart + li;
            float s = -1e30f;
            if (g >= 0 && g < L && abs(g - q) <= WIN) {
                float a = 0.f;
#pragma unroll
                for (int d = 0; d < DH; d++)
                    a = fmaf(Qsm[warp * DH + d], Ksm[li * KVS + d], a);
                s = a * scale;
            }
            sreg[c2] = s;
            mx = fmaxf(mx, s);
        }
#pragma unroll
        for (int ofs = 16; ofs; ofs >>= 1)
            mx = fmaxf(mx, __shfl_xor_sync(0xffffffffu, mx, ofs));

        float sum = 0.f;
#pragma unroll
        for (int c2 = 0; c2 < WSLOTS / 32; c2++) {
            float e = __expf(sreg[c2] - mx);   // masked slots: exp(-1e30-mx) -> 0
            Psm[warp * WSLOTS + c2 * 32 + lane] = e;
            sum += e;
        }
#pragma unroll
        for (int ofs = 16; ofs; ofs >>= 1)
            sum += __shfl_xor_sync(0xffffffffu, sum, ofs);
        __syncwarp();

        float accv = 0.f;
#pragma unroll 8
        for (int li = 0; li < WSLOTS; li++)
            accv = fmaf(Psm[warp * WSLOTS + li], Vsm[li * KVS + lane], accv);
        o[(size_t)q * D + h * DH + lane] = accv * (1.0f / sum);
        __syncwarp();
    }
}

// ---------------- launcher ----------------
extern "C" void kernel_launch(void* const* d_in, const int* in_sizes, int n_in,
                              void* d_out, int out_size) {
    const float* x     = (const float*)d_in[0];
    const float* ln1_g = (const float*)d_in[1];
    const float* ln1_b = (const float*)d_in[2];
    const float* ln2_g = (const float*)d_in[3];
    const float* ln2_b = (const float*)d_in[4];
    const float* in_w  = (const float*)d_in[5];
    const float* in_b  = (const float*)d_in[6];
    const float* out_w = (const float*)d_in[7];
    const float* out_b = (const float*)d_in[8];
    const float* w1    = (const float*)d_in[9];
    const float* b1    = (const float*)d_in[10];
    const float* w2    = (const float*)d_in[11];
    const float* b2    = (const float*)d_in[12];
    float* out = (float*)d_out;

    float *h, *qkv, *o, *x1, *h2, *f1;
    cudaGetSymbolAddress((void**)&h,   g_h);
    cudaGetSymbolAddress((void**)&qkv, g_qkv);
    cudaGetSymbolAddress((void**)&o,   g_o);
    cudaGetSymbolAddress((void**)&x1,  g_x1);
    cudaGetSymbolAddress((void**)&h2,  g_h2);
    cudaGetSymbolAddress((void**)&f1,  g_f1);

    const int smem_attn = (WSLOTS * KVS * 2 + 8 * WSLOTS + 8 * DH) * (int)sizeof(float);
    cudaFuncSetAttribute(attn_kernel, cudaFuncAttributeMaxDynamicSharedMemorySize, smem_attn);

    // 1. LN1
    ln_kernel<<<L / 8, 256>>>(x, ln1_g, ln1_b, h);
    // 2. QKV projection: [L,D] @ [3D,D]^T
    gemm_kernel<0><<<dim3(TD / BN, L / BM), 256>>>(h, in_w, in_b, nullptr, qkv, L, TD, D);
    // 3. Local-window attention
    attn_kernel<<<dim3(L / QT, H), 256, smem_attn>>>(qkv, o);
    // 4. Out projection + residual
    gemm_kernel<2><<<dim3(D / BN, L / BM), 256>>>(o, out_w, out_b, x, x1, L, D, D);
    // 5. LN2
    ln_kernel<<<L / 8, 256>>>(x1, ln2_g, ln2_b, h2);
    // 6. FFN up + exact GELU
    gemm_kernel<1><<<dim3(FF / BN, L / BM), 256>>>(h2, w1, b1, nullptr, f1, L, FF, D);
    // 7. FFN down + residual -> final output
    gemm_kernel<2><<<dim3(D / BN, L / BM), 256>>>(f1, w2, b2, x1, out, L, D, FF);
}

// round 3
// speedup vs baseline: 2.7974x; 2.7974x over previous
#include <cuda_runtime.h>
#include <cuda_bf16.h>
#include <math.h>
#include <stdint.h>

#define L 4096
#define D 256
#define H 8
#define DH 32
#define FF 1024
#define WIN 128
#define TD 768   // 3*D

// ---------------- scratch (allocation-free: __device__ globals) ----------------
__device__ __nv_bfloat16 g_hbf [L * D];    // LN1 output (bf16)
__device__ float         g_qkv [L * TD];   // QKV projection (fp32)
__device__ __nv_bfloat16 g_obf [L * D];    // attention output (bf16)
__device__ float         g_x1  [L * D];    // x + out_proj(o) (fp32)
__device__ __nv_bfloat16 g_h2bf[L * D];    // LN2 output (bf16)
__device__ __nv_bfloat16 g_f1bf[L * FF];   // gelu(h2 @ w1^T + b1) (bf16)
__device__ __nv_bfloat16 g_wqkv[TD * D];
__device__ __nv_bfloat16 g_wout[D * D];
__device__ __nv_bfloat16 g_w1  [FF * D];
__device__ __nv_bfloat16 g_w2  [D * FF];

// ================= PTX helpers (sm_80+ path: mma.sync / ldmatrix / cp.async) =================
__device__ __forceinline__ uint32_t smem_u32(const void* p) {
    uint32_t a;
    asm("{ .reg .u64 t; cvta.to.shared.u64 t, %1; cvt.u32.u64 %0, t; }" : "=r"(a) : "l"(p));
    return a;
}
__device__ __forceinline__ void cp16(uint32_t dst, const void* src) {
    asm volatile("cp.async.cg.shared.global [%0], [%1], 16;" :: "r"(dst), "l"(src));
}
#define CP_COMMIT() asm volatile("cp.async.commit_group;" ::: "memory")
#define CP_WAIT(n)  asm volatile("cp.async.wait_group %0;" :: "n"(n) : "memory")

__device__ __forceinline__ void ldm_x4(uint32_t* r, uint32_t addr) {
    asm volatile("ldmatrix.sync.aligned.m8n8.x4.shared.b16 {%0,%1,%2,%3}, [%4];"
                 : "=r"(r[0]), "=r"(r[1]), "=r"(r[2]), "=r"(r[3]) : "r"(addr));
}
__device__ __forceinline__ void mma16816(float* d, const uint32_t* a, uint32_t b0, uint32_t b1) {
    asm volatile(
        "mma.sync.aligned.m16n8k16.row.col.f32.bf16.bf16.f32 "
        "{%0,%1,%2,%3}, {%4,%5,%6,%7}, {%8,%9}, {%0,%1,%2,%3};"
        : "+f"(d[0]), "+f"(d[1]), "+f"(d[2]), "+f"(d[3])
        : "r"(a[0]), "r"(a[1]), "r"(a[2]), "r"(a[3]), "r"(b0), "r"(b1));
}

// ---------------- fp32 -> bf16 convert ----------------
__global__ void f2bf_kernel(const float* __restrict__ in, __nv_bfloat16* __restrict__ out, int n) {
    int i = blockIdx.x * blockDim.x + threadIdx.x;
    if (i < n) out[i] = __float2bfloat16(in[i]);
}

// ---------------- LayerNorm: one warp per row of 256, bf16 out ----------------
__global__ void ln_kernel(const float* __restrict__ x, const float* __restrict__ gw,
                          const float* __restrict__ bw, __nv_bfloat16* __restrict__ y) {
    int row  = (blockIdx.x * blockDim.x + threadIdx.x) >> 5;
    int lane = threadIdx.x & 31;
    if (row >= L) return;
    const float* xr = x + (size_t)row * D;
    float v[8];
    float s = 0.f;
#pragma unroll
    for (int i = 0; i < 8; i++) { v[i] = xr[lane + i * 32]; s += v[i]; }
#pragma unroll
    for (int o = 16; o; o >>= 1) s += __shfl_xor_sync(0xffffffffu, s, o);
    float mu = s * (1.0f / D);
    float vs = 0.f;
#pragma unroll
    for (int i = 0; i < 8; i++) { float d = v[i] - mu; vs += d * d; }
#pragma unroll
    for (int o = 16; o; o >>= 1) vs += __shfl_xor_sync(0xffffffffu, vs, o);
    float inv = rsqrtf(vs * (1.0f / D) + 1e-5f);
    __nv_bfloat16* yr = y + (size_t)row * D;
#pragma unroll
    for (int i = 0; i < 8; i++) {
        int c = lane + i * 32;
        yr[c] = __float2bfloat16((v[i] - mu) * inv * gw[c] + bw[c]);
    }
}

// =============== bf16 tensor-core GEMM: C[M,N] = A[M,K] @ W[N,K]^T ===============
// EPI: 0 = +bias (fp32 out), 1 = +bias+GELU (bf16 out), 2 = +bias+resid (fp32 out)
// 256 threads = 8 warps (2 x 4), block tile 128x128, warp tile 64x32, BK=64,
// cp.async double-buffered, XOR-swizzled smem (128B rows, 8 x 16B chunks).
#define TILE_BYTES 16384               // 128 rows * 128 B
#define BUF_BYTES  (2 * TILE_BYTES)    // A + W per stage
#define GSMEM_SZ   (2 * BUF_BYTES)     // double buffer = 64 KB

template <int EPI, int KDIM, bool OBF>
__global__ __launch_bounds__(256)
void gemm_mma(const __nv_bfloat16* __restrict__ A, const __nv_bfloat16* __restrict__ W,
              const float* __restrict__ bias, const float* __restrict__ resid,
              float* __restrict__ Cf, __nv_bfloat16* __restrict__ Cb, int N) {
    extern __shared__ __align__(16) char smem[];
    int tid = threadIdx.x, lane = tid & 31, wid = tid >> 5;
    int wm = wid & 1, wn = wid >> 1;   // warp coords: 2 (M) x 4 (N)
    int m0 = blockIdx.y * 128, n0 = blockIdx.x * 128;

    const __nv_bfloat16* Ab = A + (size_t)m0 * KDIM;
    const __nv_bfloat16* Wb = W + (size_t)n0 * KDIM;

    // stage one 128x64 tile of A and of W into buffer p
    auto load_tile = [&](int kt, int p) {
        char* As = smem + p * BUF_BYTES;
        char* Ws = As + TILE_BYTES;
        const __nv_bfloat16* Ag = Ab + kt * 64;
        const __nv_bfloat16* Wg = Wb + kt * 64;
#pragma unroll
        for (int rep = 0; rep < 4; rep++) {
            int cid = tid + rep * 256;               // 0..1023
            int row = cid >> 3, c = cid & 7;
            int cs = c ^ (row & 7);
            cp16(smem_u32(As + row * 128 + cs * 16), Ag + (size_t)row * KDIM + c * 8);
            cp16(smem_u32(Ws + row * 128 + cs * 16), Wg + (size_t)row * KDIM + c * 8);
        }
        CP_COMMIT();
    };

    float acc[4][4][4];
#pragma unroll
    for (int mi = 0; mi < 4; mi++)
#pragma unroll
        for (int ni = 0; ni < 4; ni++)
#pragma unroll
            for (int e = 0; e < 4; e++) acc[mi][ni][e] = 0.f;

    const int NT = KDIM / 64;
    load_tile(0, 0);
#pragma unroll 1
    for (int kt = 0; kt < NT; kt++) {
        int p = kt & 1;
        if (kt + 1 < NT) { load_tile(kt + 1, p ^ 1); CP_WAIT(1); }
        else             { CP_WAIT(0); }
        __syncthreads();

        char* As = smem + p * BUF_BYTES;
        char* Ws = As + TILE_BYTES;
#pragma unroll
        for (int ks = 0; ks < 4; ks++) {
            uint32_t afr[4][4];
#pragma unroll
            for (int mi = 0; mi < 4; mi++) {
                int row = wm * 64 + mi * 16 + (lane & 15);
                int c = ks * 2 + (lane >> 4);
                int cs = c ^ (row & 7);
                ldm_x4(afr[mi], smem_u32(As + row * 128 + cs * 16));
            }
#pragma unroll
            for (int np = 0; np < 2; np++) {
                uint32_t bfr[4];
                int row = wn * 32 + np * 16 + (lane & 15);
                int c = ks * 2 + (lane >> 4);
                int cs = c ^ (row & 7);
                ldm_x4(bfr, smem_u32(Ws + row * 128 + cs * 16));
                // bfr: [n0-7,k0-7] [n8-15,k0-7] [n0-7,k8-15] [n8-15,k8-15]
#pragma unroll
                for (int mi = 0; mi < 4; mi++) {
                    mma16816(acc[mi][np * 2 + 0], afr[mi], bfr[0], bfr[2]);
                    mma16816(acc[mi][np * 2 + 1], afr[mi], bfr[1], bfr[3]);
                }
            }
        }
        __syncthreads();
    }

    // epilogue: thread t holds (row = t/4, cols = (t%4)*2 + {0,1}) and row+8
    int qrow = lane >> 2, qcol = (lane & 3) * 2;
#pragma unroll
    for (int mi = 0; mi < 4; mi++) {
#pragma unroll
        for (int ni = 0; ni < 4; ni++) {
            int n = n0 + wn * 32 + ni * 8 + qcol;
            float b0 = bias[n], b1 = bias[n + 1];
#pragma unroll
            for (int half = 0; half < 2; half++) {
                int m = m0 + wm * 64 + mi * 16 + qrow + half * 8;
                float v0 = acc[mi][ni][half * 2 + 0] + b0;
                float v1 = acc[mi][ni][half * 2 + 1] + b1;
                if (EPI == 1) {
                    v0 = 0.5f * v0 * (1.0f + erff(v0 * 0.70710678118654752f));
                    v1 = 0.5f * v1 * (1.0f + erff(v1 * 0.70710678118654752f));
                }
                if (EPI == 2) {
                    const float2 r2 = *(const float2*)&resid[(size_t)m * N + n];
                    v0 += r2.x; v1 += r2.y;
                }
                if (OBF) {
                    __nv_bfloat162 o2;
                    o2.x = __float2bfloat16(v0); o2.y = __float2bfloat16(v1);
                    *(__nv_bfloat162*)&Cb[(size_t)m * N + n] = o2;
                } else {
                    *(float2*)&Cf[(size_t)m * N + n] = make_float2(v0, v1);
                }
            }
        }
    }
}

// ---------------- Local-window attention (scalar, 2 queries/warp) ----------------
#define QT 64
#define WSL (QT + 2 * WIN)   // 320
#define KS 36

__global__ __launch_bounds__(256)
void attn_kernel(const float* __restrict__ qkv, __nv_bfloat16* __restrict__ o) {
    extern __shared__ float sm[];
    float* Ksm = sm;                  // [320][36]
    float* Vsm = Ksm + WSL * KS;      // [320][36]
    float* Psm = Vsm + WSL * KS;      // [16][320]

    int h = blockIdx.y;
    int q0 = blockIdx.x * QT;
    int kst = q0 - WIN;
    int tid = threadIdx.x, warp = tid >> 5, lane = tid & 31;

    for (int idx = tid; idx < WSL * 8; idx += 256) {
        int row = idx >> 3, f4 = (idx & 7) * 4;
        int g = kst + row;
        float4 kv = make_float4(0.f, 0.f, 0.f, 0.f), vv = kv;
        if (g >= 0 && g < L) {
            kv = *(const float4*)(qkv + (size_t)g * TD + D     + h * DH + f4);
            vv = *(const float4*)(qkv + (size_t)g * TD + 2 * D + h * DH + f4);
        }
        *(float4*)&Ksm[row * KS + f4] = kv;
        *(float4*)&Vsm[row * KS + f4] = vv;
    }
    __syncthreads();

    const float scale = 0.17677669529663687f;  // 1/sqrt(32)
    float* Pa = &Psm[(2 * warp + 0) * WSL];
    float* Pb = &Psm[(2 * warp + 1) * WSL];

#pragma unroll 1
    for (int it = 0; it < 4; it++) {
        int qa = q0 + it * 16 + warp * 2;
        int qb = qa + 1;
        float qra[32], qrb[32];
#pragma unroll
        for (int j = 0; j < 8; j++) {
            float4 t = *(const float4*)(qkv + (size_t)qa * TD + h * DH + j * 4);
            qra[j*4] = t.x; qra[j*4+1] = t.y; qra[j*4+2] = t.z; qra[j*4+3] = t.w;
            t = *(const float4*)(qkv + (size_t)qb * TD + h * DH + j * 4);
            qrb[j*4] = t.x; qrb[j*4+1] = t.y; qrb[j*4+2] = t.z; qrb[j*4+3] = t.w;
        }
        float sa[10], sbv[10];
        float mxa = -1e30f, mxb = -1e30f;
#pragma unroll
        for (int c = 0; c < 10; c++) {
            int li = c * 32 + lane, g = kst + li;
            float a0 = 0.f, a1 = 0.f, b0 = 0.f, b1 = 0.f;
#pragma unroll
            for (int j = 0; j < 8; j++) {
                float4 k4 = *(const float4*)&Ksm[li * KS + j * 4];
                a0 = fmaf(qra[j*4+0], k4.x, a0); a1 = fmaf(qra[j*4+1], k4.y, a1);
                a0 = fmaf(qra[j*4+2], k4.z, a0); a1 = fmaf(qra[j*4+3], k4.w, a1);
                b0 = fmaf(qrb[j*4+0], k4.x, b0); b1 = fmaf(qrb[j*4+1], k4.y, b1);
                b0 = fmaf(qrb[j*4+2], k4.z, b0); b1 = fmaf(qrb[j*4+3], k4.w, b1);
            }
            bool inb = (g >= 0 && g < L);
            float va = (inb && g >= qa - WIN && g <= qa + WIN) ? (a0 + a1) * scale : -1e30f;
            float vb = (inb && g >= qb - WIN && g <= qb + WIN) ? (b0 + b1) * scale : -1e30f;
            sa[c] = va; sbv[c] = vb;
            mxa = fmaxf(mxa, va); mxb = fmaxf(mxb, vb);
        }
#pragma unroll
        for (int ofs = 16; ofs; ofs >>= 1) {
            mxa = fmaxf(mxa, __shfl_xor_sync(0xffffffffu, mxa, ofs));
            mxb = fmaxf(mxb, __shfl_xor_sync(0xffffffffu, mxb, ofs));
        }
        float suma = 0.f, sumb = 0.f;
#pragma unroll
        for (int c = 0; c < 10; c++) {
            float pa = __expf(sa[c] - mxa);
            float pb = __expf(sbv[c] - mxb);
            suma += pa; sumb += pb;
            Pa[c * 32 + lane] = pa;
            Pb[c * 32 + lane] = pb;
        }
#pragma unroll
        for (int ofs = 16; ofs; ofs >>= 1) {
            suma += __shfl_xor_sync(0xffffffffu, suma, ofs);
            sumb += __shfl_xor_sync(0xffffffffu, sumb, ofs);
        }
        __syncwarp();

        float aa0 = 0.f, aa1 = 0.f, ab0 = 0.f, ab1 = 0.f;
#pragma unroll 2
        for (int c = 0; c < 10; c++) {
#pragma unroll 8
            for (int s = 0; s < 32; s++) {
                int key = c * 32 + s;
                float v = Vsm[key * KS + lane];
                if (s & 1) { aa1 = fmaf(Pa[key], v, aa1); ab1 = fmaf(Pb[key], v, ab1); }
                else       { aa0 = fmaf(Pa[key], v, aa0); ab0 = fmaf(Pb[key], v, ab0); }
            }
        }
        o[(size_t)qa * D + h * DH + lane] = __float2bfloat16((aa0 + aa1) / suma);
        o[(size_t)qb * D + h * DH + lane] = __float2bfloat16((ab0 + ab1) / sumb);
        __syncwarp();
    }
}

// ---------------- launcher ----------------
extern "C" void kernel_launch(void* const* d_in, const int* in_sizes, int n_in,
                              void* d_out, int out_size) {
    const float* x     = (const float*)d_in[0];
    const float* ln1_g = (const float*)d_in[1];
    const float* ln1_b = (const float*)d_in[2];
    const float* ln2_g = (const float*)d_in[3];
    const float* ln2_b = (const float*)d_in[4];
    const float* in_w  = (const float*)d_in[5];
    const float* in_b  = (const float*)d_in[6];
    const float* out_w = (const float*)d_in[7];
    const float* out_b = (const float*)d_in[8];
    const float* w1    = (const float*)d_in[9];
    const float* b1    = (const float*)d_in[10];
    const float* w2    = (const float*)d_in[11];
    const float* b2    = (const float*)d_in[12];
    float* out = (float*)d_out;

    __nv_bfloat16 *hbf, *obf, *h2bf, *f1bf, *wqkv, *wout, *w1b, *w2b;
    float *qkv, *x1;
    cudaGetSymbolAddress((void**)&hbf,  g_hbf);
    cudaGetSymbolAddress((void**)&qkv,  g_qkv);
    cudaGetSymbolAddress((void**)&obf,  g_obf);
    cudaGetSymbolAddress((void**)&x1,   g_x1);
    cudaGetSymbolAddress((void**)&h2bf, g_h2bf);
    cudaGetSymbolAddress((void**)&f1bf, g_f1bf);
    cudaGetSymbolAddress((void**)&wqkv, g_wqkv);
    cudaGetSymbolAddress((void**)&wout, g_wout);
    cudaGetSymbolAddress((void**)&w1b,  g_w1);
    cudaGetSymbolAddress((void**)&w2b,  g_w2);

    const int smem_attn = (WSL * KS * 2 + 16 * WSL) * (int)sizeof(float);
    cudaFuncSetAttribute(attn_kernel, cudaFuncAttributeMaxDynamicSharedMemorySize, smem_attn);
    cudaFuncSetAttribute(gemm_mma<0, D,  false>, cudaFuncAttributeMaxDynamicSharedMemorySize, GSMEM_SZ);
    cudaFuncSetAttribute(gemm_mma<2, D,  false>, cudaFuncAttributeMaxDynamicSharedMemorySize, GSMEM_SZ);
    cudaFuncSetAttribute(gemm_mma<1, D,  true >, cudaFuncAttributeMaxDynamicSharedMemorySize, GSMEM_SZ);
    cudaFuncSetAttribute(gemm_mma<2, FF, false>, cudaFuncAttributeMaxDynamicSharedMemorySize, GSMEM_SZ);

    // weight conversions
    f2bf_kernel<<<(TD * D + 255) / 256, 256>>>(in_w, wqkv, TD * D);
    f2bf_kernel<<<(D * D + 255) / 256, 256>>>(out_w, wout, D * D);
    f2bf_kernel<<<(FF * D + 255) / 256, 256>>>(w1, w1b, FF * D);
    f2bf_kernel<<<(D * FF + 255) / 256, 256>>>(w2, w2b, D * FF);

    // 1. LN1 -> bf16
    ln_kernel<<<L / 8, 256>>>(x, ln1_g, ln1_b, hbf);
    // 2. QKV projection (tensor cores) -> fp32
    gemm_mma<0, D, false><<<dim3(TD / 128, L / 128), 256, GSMEM_SZ>>>(
        hbf, wqkv, in_b, nullptr, qkv, nullptr, TD);
    // 3. Local-window attention -> bf16
    attn_kernel<<<dim3(L / QT, H), 256, smem_attn>>>(qkv, obf);
    // 4. Out projection + residual -> fp32 x1
    gemm_mma<2, D, false><<<dim3(D / 128, L / 128), 256, GSMEM_SZ>>>(
        obf, wout, out_b, x, x1, nullptr, D);
    // 5. LN2 -> bf16
    ln_kernel<<<L / 8, 256>>>(x1, ln2_g, ln2_b, h2bf);
    // 6. FFN up + exact GELU -> bf16
    gemm_mma<1, D, true><<<dim3(FF / 128, L / 128), 256, GSMEM_SZ>>>(
        h2bf, w1b, b1, nullptr, nullptr, f1bf, FF);
    // 7. FFN down + residual -> final output (fp32)
    gemm_mma<2, FF, false><<<dim3(D / 128, L / 128), 256, GSMEM_SZ>>>(
        f1bf, w2b, b2, x1, out, nullptr, D);
}

// round 4
// speedup vs baseline: 5.0740x; 1.8138x over previous
#include <cuda_runtime.h>
#include <cuda_bf16.h>
#include <math.h>
#include <stdint.h>

#define L 4096
#define D 256
#define H 8
#define DH 32
#define FF 1024
#define WIN 128
#define TD 768   // 3*D

// ---------------- scratch (allocation-free: __device__ globals) ----------------
__device__ __nv_bfloat16 g_hbf [L * D];    // LN1 output (bf16)
__device__ __nv_bfloat16 g_qkvb[L * TD];   // QKV projection (bf16)
__device__ __nv_bfloat16 g_obf [L * D];    // attention output (bf16)
__device__ float         g_x1  [L * D];    // x + out_proj(o) (fp32)
__device__ __nv_bfloat16 g_h2bf[L * D];    // LN2 output (bf16)
__device__ __nv_bfloat16 g_f1bf[L * FF];   // gelu(h2 @ w1^T + b1) (bf16)
__device__ __nv_bfloat16 g_wqkv[TD * D];
__device__ __nv_bfloat16 g_wout[D * D];
__device__ __nv_bfloat16 g_w1  [FF * D];
__device__ __nv_bfloat16 g_w2  [D * FF];

// ================= PTX helpers (sm_80+ path: mma.sync / ldmatrix / cp.async) =================
__device__ __forceinline__ uint32_t smem_u32(const void* p) {
    uint32_t a;
    asm("{ .reg .u64 t; cvta.to.shared.u64 t, %1; cvt.u32.u64 %0, t; }" : "=r"(a) : "l"(p));
    return a;
}
__device__ __forceinline__ void cp16(uint32_t dst, const void* src) {
    asm volatile("cp.async.cg.shared.global [%0], [%1], 16;" :: "r"(dst), "l"(src));
}
__device__ __forceinline__ void cp16z(uint32_t dst, const void* src, int nbytes) {
    asm volatile("cp.async.cg.shared.global [%0], [%1], 16, %2;" :: "r"(dst), "l"(src), "r"(nbytes));
}
#define CP_COMMIT() asm volatile("cp.async.commit_group;" ::: "memory")
#define CP_WAIT(n)  asm volatile("cp.async.wait_group %0;" :: "n"(n) : "memory")

__device__ __forceinline__ void ldm_x4(uint32_t* r, uint32_t addr) {
    asm volatile("ldmatrix.sync.aligned.m8n8.x4.shared.b16 {%0,%1,%2,%3}, [%4];"
                 : "=r"(r[0]), "=r"(r[1]), "=r"(r[2]), "=r"(r[3]) : "r"(addr));
}
__device__ __forceinline__ void ldm_x4_t(uint32_t* r, uint32_t addr) {
    asm volatile("ldmatrix.sync.aligned.m8n8.x4.trans.shared.b16 {%0,%1,%2,%3}, [%4];"
                 : "=r"(r[0]), "=r"(r[1]), "=r"(r[2]), "=r"(r[3]) : "r"(addr));
}
__device__ __forceinline__ void mma16816(float* d, const uint32_t* a, uint32_t b0, uint32_t b1) {
    asm volatile(
        "mma.sync.aligned.m16n8k16.row.col.f32.bf16.bf16.f32 "
        "{%0,%1,%2,%3}, {%4,%5,%6,%7}, {%8,%9}, {%0,%1,%2,%3};"
        : "+f"(d[0]), "+f"(d[1]), "+f"(d[2]), "+f"(d[3])
        : "r"(a[0]), "r"(a[1]), "r"(a[2]), "r"(a[3]), "r"(b0), "r"(b1));
}
__device__ __forceinline__ uint32_t pack_bf2(float lo, float hi) {
    __nv_bfloat162 t = __float22bfloat162_rn(make_float2(lo, hi));
    return *(uint32_t*)&t;
}

// ---------------- fused fp32 -> bf16 weight conversion (all 4 weights) ----------------
#define SZ0 (TD * D)              // 196608
#define SZ1 (D * D)               //  65536
#define SZ2 (FF * D)              // 262144
#define SZ3 (D * FF)              // 262144
#define SZT (SZ0 + SZ1 + SZ2 + SZ3)
__global__ void f2bf4_kernel(const float* __restrict__ s0, __nv_bfloat16* __restrict__ d0,
                             const float* __restrict__ s1, __nv_bfloat16* __restrict__ d1,
                             const float* __restrict__ s2, __nv_bfloat16* __restrict__ d2,
                             const float* __restrict__ s3, __nv_bfloat16* __restrict__ d3) {
    int j = (blockIdx.x * blockDim.x + threadIdx.x) * 2;
    if (j >= SZT) return;
    const float* s; __nv_bfloat16* d; int off;
    if (j < SZ0)                 { s = s0; d = d0; off = j; }
    else if (j < SZ0 + SZ1)      { s = s1; d = d1; off = j - SZ0; }
    else if (j < SZ0 + SZ1 + SZ2){ s = s2; d = d2; off = j - SZ0 - SZ1; }
    else                         { s = s3; d = d3; off = j - SZ0 - SZ1 - SZ2; }
    float2 v = *(const float2*)(s + off);
    *(__nv_bfloat162*)(d + off) = __float22bfloat162_rn(v);
}

// ---------------- LayerNorm: one warp per row of 256, bf16 out ----------------
__global__ void ln_kernel(const float* __restrict__ x, const float* __restrict__ gw,
                          const float* __restrict__ bw, __nv_bfloat16* __restrict__ y) {
    int row  = (blockIdx.x * blockDim.x + threadIdx.x) >> 5;
    int lane = threadIdx.x & 31;
    if (row >= L) return;
    const float* xr = x + (size_t)row * D;
    float v[8];
    float s = 0.f;
#pragma unroll
    for (int i = 0; i < 8; i++) { v[i] = xr[lane + i * 32]; s += v[i]; }
#pragma unroll
    for (int o = 16; o; o >>= 1) s += __shfl_xor_sync(0xffffffffu, s, o);
    float mu = s * (1.0f / D);
    float vs = 0.f;
#pragma unroll
    for (int i = 0; i < 8; i++) { float d = v[i] - mu; vs += d * d; }
#pragma unroll
    for (int o = 16; o; o >>= 1) vs += __shfl_xor_sync(0xffffffffu, vs, o);
    float inv = rsqrtf(vs * (1.0f / D) + 1e-5f);
    __nv_bfloat16* yr = y + (size_t)row * D;
#pragma unroll
    for (int i = 0; i < 8; i++) {
        int c = lane + i * 32;
        yr[c] = __float2bfloat16((v[i] - mu) * inv * gw[c] + bw[c]);
    }
}

// =============== bf16 tensor-core GEMM: C[M,N] = A[M,K] @ W[N,K]^T ===============
#define TILE_BYTES 16384
#define BUF_BYTES  (2 * TILE_BYTES)
#define GSMEM_SZ   (2 * BUF_BYTES)

template <int EPI, int KDIM, bool OBF>
__global__ __launch_bounds__(256)
void gemm_mma(const __nv_bfloat16* __restrict__ A, const __nv_bfloat16* __restrict__ W,
              const float* __restrict__ bias, const float* __restrict__ resid,
              float* __restrict__ Cf, __nv_bfloat16* __restrict__ Cb, int N) {
    extern __shared__ __align__(16) char smem[];
    int tid = threadIdx.x, lane = tid & 31, wid = tid >> 5;
    int wm = wid & 1, wn = wid >> 1;
    int m0 = blockIdx.y * 128, n0 = blockIdx.x * 128;

    const __nv_bfloat16* Ab = A + (size_t)m0 * KDIM;
    const __nv_bfloat16* Wb = W + (size_t)n0 * KDIM;

    auto load_tile = [&](int kt, int p) {
        char* As = smem + p * BUF_BYTES;
        char* Ws = As + TILE_BYTES;
        const __nv_bfloat16* Ag = Ab + kt * 64;
        const __nv_bfloat16* Wg = Wb + kt * 64;
#pragma unroll
        for (int rep = 0; rep < 4; rep++) {
            int cid = tid + rep * 256;
            int row = cid >> 3, c = cid & 7;
            int cs = c ^ (row & 7);
            cp16(smem_u32(As + row * 128 + cs * 16), Ag + (size_t)row * KDIM + c * 8);
            cp16(smem_u32(Ws + row * 128 + cs * 16), Wg + (size_t)row * KDIM + c * 8);
        }
        CP_COMMIT();
    };

    float acc[4][4][4];
#pragma unroll
    for (int mi = 0; mi < 4; mi++)
#pragma unroll
        for (int ni = 0; ni < 4; ni++)
#pragma unroll
            for (int e = 0; e < 4; e++) acc[mi][ni][e] = 0.f;

    const int NT = KDIM / 64;
    load_tile(0, 0);
#pragma unroll 1
    for (int kt = 0; kt < NT; kt++) {
        int p = kt & 1;
        if (kt + 1 < NT) { load_tile(kt + 1, p ^ 1); CP_WAIT(1); }
        else             { CP_WAIT(0); }
        __syncthreads();

        char* As = smem + p * BUF_BYTES;
        char* Ws = As + TILE_BYTES;
#pragma unroll
        for (int ks = 0; ks < 4; ks++) {
            uint32_t afr[4][4];
#pragma unroll
            for (int mi = 0; mi < 4; mi++) {
                int row = wm * 64 + mi * 16 + (lane & 15);
                int c = ks * 2 + (lane >> 4);
                int cs = c ^ (row & 7);
                ldm_x4(afr[mi], smem_u32(As + row * 128 + cs * 16));
            }
#pragma unroll
            for (int np = 0; np < 2; np++) {
                uint32_t bfr[4];
                int row = wn * 32 + np * 16 + (lane & 15);
                int c = ks * 2 + (lane >> 4);
                int cs = c ^ (row & 7);
                ldm_x4(bfr, smem_u32(Ws + row * 128 + cs * 16));
#pragma unroll
                for (int mi = 0; mi < 4; mi++) {
                    mma16816(acc[mi][np * 2 + 0], afr[mi], bfr[0], bfr[2]);
                    mma16816(acc[mi][np * 2 + 1], afr[mi], bfr[1], bfr[3]);
                }
            }
        }
        __syncthreads();
    }

    int qrow = lane >> 2, qcol = (lane & 3) * 2;
#pragma unroll
    for (int mi = 0; mi < 4; mi++) {
#pragma unroll
        for (int ni = 0; ni < 4; ni++) {
            int n = n0 + wn * 32 + ni * 8 + qcol;
            float b0 = bias[n], b1 = bias[n + 1];
#pragma unroll
            for (int half = 0; half < 2; half++) {
                int m = m0 + wm * 64 + mi * 16 + qrow + half * 8;
                float v0 = acc[mi][ni][half * 2 + 0] + b0;
                float v1 = acc[mi][ni][half * 2 + 1] + b1;
                if (EPI == 1) {
                    v0 = 0.5f * v0 * (1.0f + erff(v0 * 0.70710678118654752f));
                    v1 = 0.5f * v1 * (1.0f + erff(v1 * 0.70710678118654752f));
                }
                if (EPI == 2) {
                    const float2 r2 = *(const float2*)&resid[(size_t)m * N + n];
                    v0 += r2.x; v1 += r2.y;
                }
                if (OBF) {
                    __nv_bfloat162 o2;
                    o2.x = __float2bfloat16(v0); o2.y = __float2bfloat16(v1);
                    *(__nv_bfloat162*)&Cb[(size_t)m * N + n] = o2;
                } else {
                    *(float2*)&Cf[(size_t)m * N + n] = make_float2(v0, v1);
                }
            }
        }
    }
}

// ============ Local-window attention (tensor cores, flash-style) ============
// Block = (64-query tile, head), 128 threads / 4 warps; warp w owns 16 queries.
// K/V window = 320 slots. Smem rows are 80 bytes (40 bf16): stride 80 mod 128
// cycles through all eight 16B groups -> every ldmatrix phase conflict-free.
#define AQT 64
#define AWS 320
#define ARS 80                         // row stride bytes
#define AQ_OFF 0
#define AK_OFF (AQT * ARS)             // 5120
#define AV_OFF (AK_OFF + AWS * ARS)    // 30720
#define ASMEM  (AV_OFF + AWS * ARS)    // 56320

__global__ __launch_bounds__(128)
void attn_mma(const __nv_bfloat16* __restrict__ qkv, __nv_bfloat16* __restrict__ o) {
    extern __shared__ __align__(16) char asm_[];
    int h = blockIdx.y;
    int q0 = blockIdx.x * AQT;
    int kst = q0 - WIN;
    int tid = threadIdx.x, warp = tid >> 5, lane = tid & 31;

    // ---- stage Q (64 rows) + K,V (320 rows each) ----
#pragma unroll 4
    for (int idx = tid; idx < 704 * 4; idx += 128) {
        int row = idx >> 2, ch = idx & 3;
        const __nv_bfloat16* src;
        uint32_t dst;
        int valid;
        if (row < 64) {
            src = qkv + (size_t)(q0 + row) * TD + h * DH + ch * 8;
            dst = smem_u32(asm_ + AQ_OFF + row * ARS + ch * 16);
            valid = 16;
        } else if (row < 384) {
            int r = row - 64, g = kst + r;
            valid = (g >= 0 && g < L) ? 16 : 0;
            src = qkv + (size_t)(valid ? g : 0) * TD + D + h * DH + ch * 8;
            dst = smem_u32(asm_ + AK_OFF + r * ARS + ch * 16);
        } else {
            int r = row - 384, g = kst + r;
            valid = (g >= 0 && g < L) ? 16 : 0;
            src = qkv + (size_t)(valid ? g : 0) * TD + 2 * D + h * DH + ch * 8;
            dst = smem_u32(asm_ + AV_OFF + r * ARS + ch * 16);
        }
        cp16z(dst, src, valid);
    }
    CP_COMMIT();
    CP_WAIT(0);
    __syncthreads();

    const int qb = warp * 16;
    // ---- Q fragments (once) ----
    uint32_t aq[2][4];
#pragma unroll
    for (int ks = 0; ks < 2; ks++) {
        uint32_t addr = smem_u32(asm_ + AQ_OFF + (qb + (lane & 15)) * ARS + ks * 32 + (lane >> 4) * 16);
        ldm_x4(aq[ks], addr);
    }

    // per-lane row params (rows r0 = lane/4, r0+8 within warp tile)
    int r0 = lane >> 2;
    int lo0 = max(qb + r0, -kst),       hi0 = min(qb + r0 + 2 * WIN, (L - 1) - kst);
    int lo1 = max(qb + r0 + 8, -kst),   hi1 = min(qb + r0 + 8 + 2 * WIN, (L - 1) - kst);

    const float scale = 0.17677669529663687f;  // 1/sqrt(32)
    const float NEG = -1e30f;
    float m0 = NEG, m1 = NEG, l0 = 0.f, l1 = 0.f;
    float acc[4][4];
#pragma unroll
    for (int dt = 0; dt < 4; dt++)
#pragma unroll
        for (int e = 0; e < 4; e++) acc[dt][e] = 0.f;

#pragma unroll 1
    for (int c = 0; c < 5; c++) {
        // ---- S = Q K^T (16 x 64), fp32 acc ----
        float sfr[8][4];
#pragma unroll
        for (int nt = 0; nt < 8; nt++)
#pragma unroll
            for (int e = 0; e < 4; e++) sfr[nt][e] = 0.f;
#pragma unroll
        for (int ks = 0; ks < 2; ks++) {
#pragma unroll
            for (int p = 0; p < 4; p++) {
                uint32_t b[4];
                uint32_t addr = smem_u32(asm_ + AK_OFF + (c * 64 + p * 16 + (lane & 15)) * ARS
                                         + ks * 32 + (lane >> 4) * 16);
                ldm_x4(b, addr);
                mma16816(sfr[2 * p],     aq[ks], b[0], b[2]);
                mma16816(sfr[2 * p + 1], aq[ks], b[1], b[3]);
            }
        }
        // ---- mask + scale + chunk max ----
        float cm0 = NEG, cm1 = NEG;
#pragma unroll
        for (int nt = 0; nt < 8; nt++) {
            int base = c * 64 + nt * 8 + (lane & 3) * 2;
            sfr[nt][0] = (base     >= lo0 && base     <= hi0) ? sfr[nt][0] * scale : NEG;
            sfr[nt][1] = (base + 1 >= lo0 && base + 1 <= hi0) ? sfr[nt][1] * scale : NEG;
            sfr[nt][2] = (base     >= lo1 && base     <= hi1) ? sfr[nt][2] * scale : NEG;
            sfr[nt][3] = (base + 1 >= lo1 && base + 1 <= hi1) ? sfr[nt][3] * scale : NEG;
            cm0 = fmaxf(cm0, fmaxf(sfr[nt][0], sfr[nt][1]));
            cm1 = fmaxf(cm1, fmaxf(sfr[nt][2], sfr[nt][3]));
        }
        cm0 = fmaxf(cm0, __shfl_xor_sync(0xffffffffu, cm0, 1));
        cm0 = fmaxf(cm0, __shfl_xor_sync(0xffffffffu, cm0, 2));
        cm1 = fmaxf(cm1, __shfl_xor_sync(0xffffffffu, cm1, 1));
        cm1 = fmaxf(cm1, __shfl_xor_sync(0xffffffffu, cm1, 2));
        // ---- online softmax update ----
        float m0n = fmaxf(m0, cm0), m1n = fmaxf(m1, cm1);
        float cr0 = __expf(m0 - m0n), cr1 = __expf(m1 - m1n);
#pragma unroll
        for (int dt = 0; dt < 4; dt++) {
            acc[dt][0] *= cr0; acc[dt][1] *= cr0;
            acc[dt][2] *= cr1; acc[dt][3] *= cr1;
        }
        float rs0 = 0.f, rs1 = 0.f;
#pragma unroll
        for (int nt = 0; nt < 8; nt++) {
            float p0 = __expf(sfr[nt][0] - m0n);
            float p1 = __expf(sfr[nt][1] - m0n);
            float p2 = __expf(sfr[nt][2] - m1n);
            float p3 = __expf(sfr[nt][3] - m1n);
            sfr[nt][0] = p0; sfr[nt][1] = p1; sfr[nt][2] = p2; sfr[nt][3] = p3;
            rs0 += p0 + p1; rs1 += p2 + p3;
        }
        rs0 += __shfl_xor_sync(0xffffffffu, rs0, 1);
        rs0 += __shfl_xor_sync(0xffffffffu, rs0, 2);
        rs1 += __shfl_xor_sync(0xffffffffu, rs1, 1);
        rs1 += __shfl_xor_sync(0xffffffffu, rs1, 2);
        l0 = l0 * cr0 + rs0;
        l1 = l1 * cr1 + rs1;
        m0 = m0n; m1 = m1n;
        // ---- acc += P V (16 x 64 @ 64 x 32) ----
#pragma unroll
        for (int s = 0; s < 4; s++) {
            uint32_t pa[4];
            pa[0] = pack_bf2(sfr[2 * s][0],     sfr[2 * s][1]);
            pa[1] = pack_bf2(sfr[2 * s][2],     sfr[2 * s][3]);
            pa[2] = pack_bf2(sfr[2 * s + 1][0], sfr[2 * s + 1][1]);
            pa[3] = pack_bf2(sfr[2 * s + 1][2], sfr[2 * s + 1][3]);
#pragma unroll
            for (int dp = 0; dp < 2; dp++) {
                uint32_t b[4];
                uint32_t addr = smem_u32(asm_ + AV_OFF + (c * 64 + s * 16 + (lane & 15)) * ARS
                                         + dp * 32 + (lane >> 4) * 16);
                ldm_x4_t(b, addr);
                mma16816(acc[2 * dp],     pa, b[0], b[1]);
                mma16816(acc[2 * dp + 1], pa, b[2], b[3]);
            }
        }
    }

    // ---- normalize + store ----
    float inv0 = 1.0f / l0, inv1 = 1.0f / l1;
    int gq0 = q0 + qb + r0, gq1 = gq0 + 8;
#pragma unroll
    for (int dt = 0; dt < 4; dt++) {
        int d = h * DH + dt * 8 + (lane & 3) * 2;
        __nv_bfloat162 o0 = __float22bfloat162_rn(make_float2(acc[dt][0] * inv0, acc[dt][1] * inv0));
        __nv_bfloat162 o1 = __float22bfloat162_rn(make_float2(acc[dt][2] * inv1, acc[dt][3] * inv1));
        *(__nv_bfloat162*)&o[(size_t)gq0 * D + d] = o0;
        *(__nv_bfloat162*)&o[(size_t)gq1 * D + d] = o1;
    }
}

// ---------------- launcher ----------------
extern "C" void kernel_launch(void* const* d_in, const int* in_sizes, int n_in,
                              void* d_out, int out_size) {
    const float* x     = (const float*)d_in[0];
    const float* ln1_g = (const float*)d_in[1];
    const float* ln1_b = (const float*)d_in[2];
    const float* ln2_g = (const float*)d_in[3];
    const float* ln2_b = (const float*)d_in[4];
    const float* in_w  = (const float*)d_in[5];
    const float* in_b  = (const float*)d_in[6];
    const float* out_w = (const float*)d_in[7];
    const float* out_b = (const float*)d_in[8];
    const float* w1    = (const float*)d_in[9];
    const float* b1    = (const float*)d_in[10];
    const float* w2    = (const float*)d_in[11];
    const float* b2    = (const float*)d_in[12];
    float* out = (float*)d_out;

    __nv_bfloat16 *hbf, *qkvb, *obf, *h2bf, *f1bf, *wqkv, *wout, *w1b, *w2b;
    float *x1;
    cudaGetSymbolAddress((void**)&hbf,  g_hbf);
    cudaGetSymbolAddress((void**)&qkvb, g_qkvb);
    cudaGetSymbolAddress((void**)&obf,  g_obf);
    cudaGetSymbolAddress((void**)&x1,   g_x1);
    cudaGetSymbolAddress((void**)&h2bf, g_h2bf);
    cudaGetSymbolAddress((void**)&f1bf, g_f1bf);
    cudaGetSymbolAddress((void**)&wqkv, g_wqkv);
    cudaGetSymbolAddress((void**)&wout, g_wout);
    cudaGetSymbolAddress((void**)&w1b,  g_w1);
    cudaGetSymbolAddress((void**)&w2b,  g_w2);

    cudaFuncSetAttribute(attn_mma, cudaFuncAttributeMaxDynamicSharedMemorySize, ASMEM);
    cudaFuncSetAttribute(gemm_mma<0, D,  true >, cudaFuncAttributeMaxDynamicSharedMemorySize, GSMEM_SZ);
    cudaFuncSetAttribute(gemm_mma<2, D,  false>, cudaFuncAttributeMaxDynamicSharedMemorySize, GSMEM_SZ);
    cudaFuncSetAttribute(gemm_mma<1, D,  true >, cudaFuncAttributeMaxDynamicSharedMemorySize, GSMEM_SZ);
    cudaFuncSetAttribute(gemm_mma<2, FF, false>, cudaFuncAttributeMaxDynamicSharedMemorySize, GSMEM_SZ);

    // fused weight conversions
    f2bf4_kernel<<<(SZT / 2 + 255) / 256, 256>>>(in_w, wqkv, out_w, wout, w1, w1b, w2, w2b);

    // 1. LN1 -> bf16
    ln_kernel<<<L / 8, 256>>>(x, ln1_g, ln1_b, hbf);
    // 2. QKV projection (tensor cores) -> bf16
    gemm_mma<0, D, true><<<dim3(TD / 128, L / 128), 256, GSMEM_SZ>>>(
        hbf, wqkv, in_b, nullptr, nullptr, qkvb, TD);
    // 3. Local-window attention (tensor cores) -> bf16
    attn_mma<<<dim3(L / AQT, H), 128, ASMEM>>>(qkvb, obf);
    // 4. Out projection + residual -> fp32 x1
    gemm_mma<2, D, false><<<dim3(D / 128, L / 128), 256, GSMEM_SZ>>>(
        obf, wout, out_b, x, x1, nullptr, D);
    // 5. LN2 -> bf16
    ln_kernel<<<L / 8, 256>>>(x1, ln2_g, ln2_b, h2bf);
    // 6. FFN up + exact GELU -> bf16
    gemm_mma<1, D, true><<<dim3(FF / 128, L / 128), 256, GSMEM_SZ>>>(
        h2bf, w1b, b1, nullptr, nullptr, f1bf, FF);
    // 7. FFN down + residual -> final output (fp32)
    gemm_mma<2, FF, false><<<dim3(D / 128, L / 128), 256, GSMEM_SZ>>>(
        f1bf, w2b, b2, x1, out, nullptr, D);
}

// round 5
// speedup vs baseline: 6.0955x; 1.2013x over previous
#include <cuda_runtime.h>
#include <cuda_bf16.h>
#include <math.h>
#include <stdint.h>

#define L 4096
#define D 256
#define H 8
#define DH 32
#define FF 1024
#define WIN 128
#define TD 768   // 3*D

// ---------------- scratch (allocation-free: __device__ globals) ----------------
__device__ __nv_bfloat16 g_hbf [L * D];
__device__ __nv_bfloat16 g_qkvb[L * TD];
__device__ __nv_bfloat16 g_obf [L * D];
__device__ float         g_x1  [L * D];
__device__ __nv_bfloat16 g_h2bf[L * D];
__device__ __nv_bfloat16 g_f1bf[L * FF];
__device__ __nv_bfloat16 g_wqkv[TD * D];
__device__ __nv_bfloat16 g_wout[D * D];
__device__ __nv_bfloat16 g_w1  [FF * D];
__device__ __nv_bfloat16 g_w2  [D * FF];

// ================= PTX helpers =================
__device__ __forceinline__ uint32_t smem_u32(const void* p) {
    uint32_t a;
    asm("{ .reg .u64 t; cvta.to.shared.u64 t, %1; cvt.u32.u64 %0, t; }" : "=r"(a) : "l"(p));
    return a;
}
__device__ __forceinline__ void cp16(uint32_t dst, const void* src) {
    asm volatile("cp.async.cg.shared.global [%0], [%1], 16;" :: "r"(dst), "l"(src));
}
__device__ __forceinline__ void cp16z(uint32_t dst, const void* src, int nbytes) {
    asm volatile("cp.async.cg.shared.global [%0], [%1], 16, %2;" :: "r"(dst), "l"(src), "r"(nbytes));
}
#define CP_COMMIT() asm volatile("cp.async.commit_group;" ::: "memory")
#define CP_WAIT(n)  asm volatile("cp.async.wait_group %0;" :: "n"(n) : "memory")

__device__ __forceinline__ void ldm_x4(uint32_t* r, uint32_t addr) {
    asm volatile("ldmatrix.sync.aligned.m8n8.x4.shared.b16 {%0,%1,%2,%3}, [%4];"
                 : "=r"(r[0]), "=r"(r[1]), "=r"(r[2]), "=r"(r[3]) : "r"(addr));
}
__device__ __forceinline__ void ldm_x4_t(uint32_t* r, uint32_t addr) {
    asm volatile("ldmatrix.sync.aligned.m8n8.x4.trans.shared.b16 {%0,%1,%2,%3}, [%4];"
                 : "=r"(r[0]), "=r"(r[1]), "=r"(r[2]), "=r"(r[3]) : "r"(addr));
}
__device__ __forceinline__ void mma16816(float* d, const uint32_t* a, uint32_t b0, uint32_t b1) {
    asm volatile(
        "mma.sync.aligned.m16n8k16.row.col.f32.bf16.bf16.f32 "
        "{%0,%1,%2,%3}, {%4,%5,%6,%7}, {%8,%9}, {%0,%1,%2,%3};"
        : "+f"(d[0]), "+f"(d[1]), "+f"(d[2]), "+f"(d[3])
        : "r"(a[0]), "r"(a[1]), "r"(a[2]), "r"(a[3]), "r"(b0), "r"(b1));
}
__device__ __forceinline__ uint32_t pack_bf2(float lo, float hi) {
    __nv_bfloat162 t = __float22bfloat162_rn(make_float2(lo, hi));
    return *(uint32_t*)&t;
}

// ---------------- fused fp32 -> bf16 weight conversion ----------------
#define SZ0 (TD * D)
#define SZ1 (D * D)
#define SZ2 (FF * D)
#define SZ3 (D * FF)
#define SZT (SZ0 + SZ1 + SZ2 + SZ3)
__global__ void f2bf4_kernel(const float* __restrict__ s0, __nv_bfloat16* __restrict__ d0,
                             const float* __restrict__ s1, __nv_bfloat16* __restrict__ d1,
                             const float* __restrict__ s2, __nv_bfloat16* __restrict__ d2,
                             const float* __restrict__ s3, __nv_bfloat16* __restrict__ d3) {
    int j = (blockIdx.x * blockDim.x + threadIdx.x) * 4;
    if (j >= SZT) return;
    const float* s; __nv_bfloat16* d; int off;
    if (j < SZ0)                 { s = s0; d = d0; off = j; }
    else if (j < SZ0 + SZ1)      { s = s1; d = d1; off = j - SZ0; }
    else if (j < SZ0 + SZ1 + SZ2){ s = s2; d = d2; off = j - SZ0 - SZ1; }
    else                         { s = s3; d = d3; off = j - SZ0 - SZ1 - SZ2; }
    float4 v = *(const float4*)(s + off);
    __nv_bfloat162 a = __float22bfloat162_rn(make_float2(v.x, v.y));
    __nv_bfloat162 b = __float22bfloat162_rn(make_float2(v.z, v.w));
    *(__nv_bfloat162*)(d + off)     = a;
    *(__nv_bfloat162*)(d + off + 2) = b;
}

// ---------------- LayerNorm: one warp per row of 256, bf16 out ----------------
__global__ void ln_kernel(const float* __restrict__ x, const float* __restrict__ gw,
                          const float* __restrict__ bw, __nv_bfloat16* __restrict__ y) {
    int row  = (blockIdx.x * blockDim.x + threadIdx.x) >> 5;
    int lane = threadIdx.x & 31;
    if (row >= L) return;
    const float* xr = x + (size_t)row * D;
    float4 v0 = *(const float4*)(xr + lane * 4);
    float4 v1 = *(const float4*)(xr + 128 + lane * 4);
    float s = v0.x + v0.y + v0.z + v0.w + v1.x + v1.y + v1.z + v1.w;
#pragma unroll
    for (int o = 16; o; o >>= 1) s += __shfl_xor_sync(0xffffffffu, s, o);
    float mu = s * (1.0f / D);
    float vs = 0.f;
    {
        float d;
        d = v0.x - mu; vs += d * d; d = v0.y - mu; vs += d * d;
        d = v0.z - mu; vs += d * d; d = v0.w - mu; vs += d * d;
        d = v1.x - mu; vs += d * d; d = v1.y - mu; vs += d * d;
        d = v1.z - mu; vs += d * d; d = v1.w - mu; vs += d * d;
    }
#pragma unroll
    for (int o = 16; o; o >>= 1) vs += __shfl_xor_sync(0xffffffffu, vs, o);
    float inv = rsqrtf(vs * (1.0f / D) + 1e-5f);
    __nv_bfloat16* yr = y + (size_t)row * D;
    int c0 = lane * 4, c1 = 128 + lane * 4;
    const float4 g0 = *(const float4*)(gw + c0), g1 = *(const float4*)(gw + c1);
    const float4 b0 = *(const float4*)(bw + c0), b1 = *(const float4*)(bw + c1);
    *(__nv_bfloat162*)(yr + c0)     = __float22bfloat162_rn(make_float2(
        (v0.x - mu) * inv * g0.x + b0.x, (v0.y - mu) * inv * g0.y + b0.y));
    *(__nv_bfloat162*)(yr + c0 + 2) = __float22bfloat162_rn(make_float2(
        (v0.z - mu) * inv * g0.z + b0.z, (v0.w - mu) * inv * g0.w + b0.w));
    *(__nv_bfloat162*)(yr + c1)     = __float22bfloat162_rn(make_float2(
        (v1.x - mu) * inv * g1.x + b1.x, (v1.y - mu) * inv * g1.y + b1.y));
    *(__nv_bfloat162*)(yr + c1 + 2) = __float22bfloat162_rn(make_float2(
        (v1.z - mu) * inv * g1.z + b1.z, (v1.w - mu) * inv * g1.w + b1.w));
}

// =============== bf16 tensor-core GEMM: C[M,N] = A[M,K] @ W[N,K]^T ===============
// Templated block-M: BM=128 (2x4 warps, 64x32 warp tiles) or BM=64 (32x32 tiles).
template <int EPI, int KDIM, bool OBF, int BM>
__global__ __launch_bounds__(256)
void gemm_mma(const __nv_bfloat16* __restrict__ A, const __nv_bfloat16* __restrict__ W,
              const float* __restrict__ bias, const float* __restrict__ resid,
              float* __restrict__ Cf, __nv_bfloat16* __restrict__ Cb, int N) {
    constexpr int WM = BM / 2;           // warp M tile
    constexpr int MI = WM / 16;          // m16 frags per warp
    constexpr int ABYTES = BM * 128;
    constexpr int BUF = ABYTES + 16384;  // A + W per stage
    extern __shared__ __align__(16) char smem[];
    int tid = threadIdx.x, lane = tid & 31, wid = tid >> 5;
    int wm = wid & 1, wn = wid >> 1;
    int m0 = blockIdx.y * BM, n0 = blockIdx.x * 128;

    const __nv_bfloat16* Ab = A + (size_t)m0 * KDIM;
    const __nv_bfloat16* Wb = W + (size_t)n0 * KDIM;

    auto load_tile = [&](int kt, int p) {
        char* As = smem + p * BUF;
        char* Ws = As + ABYTES;
        const __nv_bfloat16* Ag = Ab + kt * 64;
        const __nv_bfloat16* Wg = Wb + kt * 64;
#pragma unroll
        for (int rep = 0; rep < BM * 8 / 256; rep++) {
            int cid = tid + rep * 256;
            int row = cid >> 3, c = cid & 7;
            int cs = c ^ (row & 7);
            cp16(smem_u32(As + row * 128 + cs * 16), Ag + (size_t)row * KDIM + c * 8);
        }
#pragma unroll
        for (int rep = 0; rep < 4; rep++) {
            int cid = tid + rep * 256;
            int row = cid >> 3, c = cid & 7;
            int cs = c ^ (row & 7);
            cp16(smem_u32(Ws + row * 128 + cs * 16), Wg + (size_t)row * KDIM + c * 8);
        }
        CP_COMMIT();
    };

    float acc[MI][4][4];
#pragma unroll
    for (int mi = 0; mi < MI; mi++)
#pragma unroll
        for (int ni = 0; ni < 4; ni++)
#pragma unroll
            for (int e = 0; e < 4; e++) acc[mi][ni][e] = 0.f;

    const int NT = KDIM / 64;
    load_tile(0, 0);
#pragma unroll 1
    for (int kt = 0; kt < NT; kt++) {
        int p = kt & 1;
        if (kt + 1 < NT) { load_tile(kt + 1, p ^ 1); CP_WAIT(1); }
        else             { CP_WAIT(0); }
        __syncthreads();

        char* As = smem + p * BUF;
        char* Ws = As + ABYTES;
#pragma unroll
        for (int ks = 0; ks < 4; ks++) {
            uint32_t afr[MI][4];
#pragma unroll
            for (int mi = 0; mi < MI; mi++) {
                int row = wm * WM + mi * 16 + (lane & 15);
                int c = ks * 2 + (lane >> 4);
                int cs = c ^ (row & 7);
                ldm_x4(afr[mi], smem_u32(As + row * 128 + cs * 16));
            }
#pragma unroll
            for (int np = 0; np < 2; np++) {
                uint32_t bfr[4];
                int row = wn * 32 + np * 16 + (lane & 15);
                int c = ks * 2 + (lane >> 4);
                int cs = c ^ (row & 7);
                ldm_x4(bfr, smem_u32(Ws + row * 128 + cs * 16));
#pragma unroll
                for (int mi = 0; mi < MI; mi++) {
                    mma16816(acc[mi][np * 2 + 0], afr[mi], bfr[0], bfr[2]);
                    mma16816(acc[mi][np * 2 + 1], afr[mi], bfr[1], bfr[3]);
                }
            }
        }
        __syncthreads();
    }

    int qrow = lane >> 2, qcol = (lane & 3) * 2;
#pragma unroll
    for (int mi = 0; mi < MI; mi++) {
#pragma unroll
        for (int ni = 0; ni < 4; ni++) {
            int n = n0 + wn * 32 + ni * 8 + qcol;
            float b0 = bias[n], b1 = bias[n + 1];
#pragma unroll
            for (int half = 0; half < 2; half++) {
                int m = m0 + wm * WM + mi * 16 + qrow + half * 8;
                float v0 = acc[mi][ni][half * 2 + 0] + b0;
                float v1 = acc[mi][ni][half * 2 + 1] + b1;
                if (EPI == 1) {
                    v0 = 0.5f * v0 * (1.0f + erff(v0 * 0.70710678118654752f));
                    v1 = 0.5f * v1 * (1.0f + erff(v1 * 0.70710678118654752f));
                }
                if (EPI == 2) {
                    const float2 r2 = *(const float2*)&resid[(size_t)m * N + n];
                    v0 += r2.x; v1 += r2.y;
                }
                if (OBF) {
                    __nv_bfloat162 o2;
                    o2.x = __float2bfloat16(v0); o2.y = __float2bfloat16(v1);
                    *(__nv_bfloat162*)&Cb[(size_t)m * N + n] = o2;
                } else {
                    *(float2*)&Cf[(size_t)m * N + n] = make_float2(v0, v1);
                }
            }
        }
    }
}

// ============ Local-window attention (tensor cores, flash-style) ============
// Block = (128-query tile, head), 256 threads / 8 warps; warp w owns 16 queries.
// Window slots = 384; each warp touches exactly 5 of 6 key-chunks of 64.
// Smem rows are 80 bytes: stride 80 mod 128 cycles all eight 16B groups ->
// every ldmatrix phase is bank-conflict-free.
#define AQT 128
#define AWS 384
#define ARS 80
#define AQ_OFF 0
#define AK_OFF (AQT * ARS)             // 10240
#define AV_OFF (AK_OFF + AWS * ARS)    // 40960
#define ASMEM  (AV_OFF + AWS * ARS)    // 71680

__global__ __launch_bounds__(256)
void attn_mma(const __nv_bfloat16* __restrict__ qkv, __nv_bfloat16* __restrict__ o) {
    extern __shared__ __align__(16) char asm_[];
    int h = blockIdx.y;
    int q0 = blockIdx.x * AQT;
    int kst = q0 - WIN;
    int tid = threadIdx.x, warp = tid >> 5, lane = tid & 31;

    // ---- stage Q (128 rows) + K,V (384 rows each) ----
#pragma unroll 2
    for (int idx = tid; idx < 896 * 4; idx += 256) {
        int row = idx >> 2, ch = idx & 3;
        const __nv_bfloat16* src;
        uint32_t dst;
        int valid;
        if (row < 128) {
            src = qkv + (size_t)(q0 + row) * TD + h * DH + ch * 8;
            dst = smem_u32(asm_ + AQ_OFF + row * ARS + ch * 16);
            valid = 16;
        } else if (row < 512) {
            int r = row - 128, g = kst + r;
            valid = (g >= 0 && g < L) ? 16 : 0;
            src = qkv + (size_t)(valid ? g : 0) * TD + D + h * DH + ch * 8;
            dst = smem_u32(asm_ + AK_OFF + r * ARS + ch * 16);
        } else {
            int r = row - 512, g = kst + r;
            valid = (g >= 0 && g < L) ? 16 : 0;
            src = qkv + (size_t)(valid ? g : 0) * TD + 2 * D + h * DH + ch * 8;
            dst = smem_u32(asm_ + AV_OFF + r * ARS + ch * 16);
        }
        cp16z(dst, src, valid);
    }
    CP_COMMIT();
    CP_WAIT(0);
    __syncthreads();

    const int qb = warp * 16;
    const int c_lo = qb >> 6;          // warp's first key-chunk (5 chunks total)
    // ---- Q fragments (once) ----
    uint32_t aq[2][4];
#pragma unroll
    for (int ks = 0; ks < 2; ks++) {
        uint32_t addr = smem_u32(asm_ + AQ_OFF + (qb + (lane & 15)) * ARS + ks * 32 + (lane >> 4) * 16);
        ldm_x4(aq[ks], addr);
    }

    int r0 = lane >> 2;
    int lo0 = max(qb + r0, -kst),       hi0 = min(qb + r0 + 2 * WIN, (L - 1) - kst);
    int lo1 = max(qb + r0 + 8, -kst),   hi1 = min(qb + r0 + 8 + 2 * WIN, (L - 1) - kst);

    const float scale = 0.17677669529663687f;
    const float NEG = -1e30f;
    float m0 = NEG, m1 = NEG, l0 = 0.f, l1 = 0.f;
    float acc[4][4];
#pragma unroll
    for (int dt = 0; dt < 4; dt++)
#pragma unroll
        for (int e = 0; e < 4; e++) acc[dt][e] = 0.f;

#pragma unroll 1
    for (int cc = 0; cc < 5; cc++) {
        int c = c_lo + cc;
        // ---- S = Q K^T (16 x 64) ----
        float sfr[8][4];
#pragma unroll
        for (int nt = 0; nt < 8; nt++)
#pragma unroll
            for (int e = 0; e < 4; e++) sfr[nt][e] = 0.f;
#pragma unroll
        for (int ks = 0; ks < 2; ks++) {
#pragma unroll
            for (int p = 0; p < 4; p++) {
                uint32_t b[4];
                uint32_t addr = smem_u32(asm_ + AK_OFF + (c * 64 + p * 16 + (lane & 15)) * ARS
                                         + ks * 32 + (lane >> 4) * 16);
                ldm_x4(b, addr);
                mma16816(sfr[2 * p],     aq[ks], b[0], b[2]);
                mma16816(sfr[2 * p + 1], aq[ks], b[1], b[3]);
            }
        }
        // ---- mask + scale + chunk max ----
        float cm0 = NEG, cm1 = NEG;
#pragma unroll
        for (int nt = 0; nt < 8; nt++) {
            int base = c * 64 + nt * 8 + (lane & 3) * 2;
            sfr[nt][0] = (base     >= lo0 && base     <= hi0) ? sfr[nt][0] * scale : NEG;
            sfr[nt][1] = (base + 1 >= lo0 && base + 1 <= hi0) ? sfr[nt][1] * scale : NEG;
            sfr[nt][2] = (base     >= lo1 && base     <= hi1) ? sfr[nt][2] * scale : NEG;
            sfr[nt][3] = (base + 1 >= lo1 && base + 1 <= hi1) ? sfr[nt][3] * scale : NEG;
            cm0 = fmaxf(cm0, fmaxf(sfr[nt][0], sfr[nt][1]));
            cm1 = fmaxf(cm1, fmaxf(sfr[nt][2], sfr[nt][3]));
        }
        cm0 = fmaxf(cm0, __shfl_xor_sync(0xffffffffu, cm0, 1));
        cm0 = fmaxf(cm0, __shfl_xor_sync(0xffffffffu, cm0, 2));
        cm1 = fmaxf(cm1, __shfl_xor_sync(0xffffffffu, cm1, 1));
        cm1 = fmaxf(cm1, __shfl_xor_sync(0xffffffffu, cm1, 2));
        // ---- online softmax ----
        float m0n = fmaxf(m0, cm0), m1n = fmaxf(m1, cm1);
        float cr0 = __expf(m0 - m0n), cr1 = __expf(m1 - m1n);
#pragma unroll
        for (int dt = 0; dt < 4; dt++) {
            acc[dt][0] *= cr0; acc[dt][1] *= cr0;
            acc[dt][2] *= cr1; acc[dt][3] *= cr1;
        }
        float rs0 = 0.f, rs1 = 0.f;
#pragma unroll
        for (int nt = 0; nt < 8; nt++) {
            float p0 = __expf(sfr[nt][0] - m0n);
            float p1 = __expf(sfr[nt][1] - m0n);
            float p2 = __expf(sfr[nt][2] - m1n);
            float p3 = __expf(sfr[nt][3] - m1n);
            sfr[nt][0] = p0; sfr[nt][1] = p1; sfr[nt][2] = p2; sfr[nt][3] = p3;
            rs0 += p0 + p1; rs1 += p2 + p3;
        }
        rs0 += __shfl_xor_sync(0xffffffffu, rs0, 1);
        rs0 += __shfl_xor_sync(0xffffffffu, rs0, 2);
        rs1 += __shfl_xor_sync(0xffffffffu, rs1, 1);
        rs1 += __shfl_xor_sync(0xffffffffu, rs1, 2);
        l0 = l0 * cr0 + rs0;
        l1 = l1 * cr1 + rs1;
        m0 = m0n; m1 = m1n;
        // ---- acc += P V ----
#pragma unroll
        for (int s = 0; s < 4; s++) {
            uint32_t pa[4];
            pa[0] = pack_bf2(sfr[2 * s][0],     sfr[2 * s][1]);
            pa[1] = pack_bf2(sfr[2 * s][2],     sfr[2 * s][3]);
            pa[2] = pack_bf2(sfr[2 * s + 1][0], sfr[2 * s + 1][1]);
            pa[3] = pack_bf2(sfr[2 * s + 1][2], sfr[2 * s + 1][3]);
#pragma unroll
            for (int dp = 0; dp < 2; dp++) {
                uint32_t b[4];
                uint32_t addr = smem_u32(asm_ + AV_OFF + (c * 64 + s * 16 + (lane & 15)) * ARS
                                         + dp * 32 + (lane >> 4) * 16);
                ldm_x4_t(b, addr);
                mma16816(acc[2 * dp],     pa, b[0], b[1]);
                mma16816(acc[2 * dp + 1], pa, b[2], b[3]);
            }
        }
    }

    // ---- normalize + store ----
    float inv0 = 1.0f / l0, inv1 = 1.0f / l1;
    int gq0 = q0 + qb + r0, gq1 = gq0 + 8;
#pragma unroll
    for (int dt = 0; dt < 4; dt++) {
        int d = h * DH + dt * 8 + (lane & 3) * 2;
        __nv_bfloat162 o0 = __float22bfloat162_rn(make_float2(acc[dt][0] * inv0, acc[dt][1] * inv0));
        __nv_bfloat162 o1 = __float22bfloat162_rn(make_float2(acc[dt][2] * inv1, acc[dt][3] * inv1));
        *(__nv_bfloat162*)&o[(size_t)gq0 * D + d] = o0;
        *(__nv_bfloat162*)&o[(size_t)gq1 * D + d] = o1;
    }
}

// ---------------- launcher ----------------
extern "C" void kernel_launch(void* const* d_in, const int* in_sizes, int n_in,
                              void* d_out, int out_size) {
    const float* x     = (const float*)d_in[0];
    const float* ln1_g = (const float*)d_in[1];
    const float* ln1_b = (const float*)d_in[2];
    const float* ln2_g = (const float*)d_in[3];
    const float* ln2_b = (const float*)d_in[4];
    const float* in_w  = (const float*)d_in[5];
    const float* in_b  = (const float*)d_in[6];
    const float* out_w = (const float*)d_in[7];
    const float* out_b = (const float*)d_in[8];
    const float* w1    = (const float*)d_in[9];
    const float* b1    = (const float*)d_in[10];
    const float* w2    = (const float*)d_in[11];
    const float* b2    = (const float*)d_in[12];
    float* out = (float*)d_out;

    __nv_bfloat16 *hbf, *qkvb, *obf, *h2bf, *f1bf, *wqkv, *wout, *w1b, *w2b;
    float *x1;
    cudaGetSymbolAddress((void**)&hbf,  g_hbf);
    cudaGetSymbolAddress((void**)&qkvb, g_qkvb);
    cudaGetSymbolAddress((void**)&obf,  g_obf);
    cudaGetSymbolAddress((void**)&x1,   g_x1);
    cudaGetSymbolAddress((void**)&h2bf, g_h2bf);
    cudaGetSymbolAddress((void**)&f1bf, g_f1bf);
    cudaGetSymbolAddress((void**)&wqkv, g_wqkv);
    cudaGetSymbolAddress((void**)&wout, g_wout);
    cudaGetSymbolAddress((void**)&w1b,  g_w1);
    cudaGetSymbolAddress((void**)&w2b,  g_w2);

    const int SM128 = 2 * (128 * 128 + 16384);   // 65536
    const int SM64  = 2 * (64 * 128 + 16384);    // 49152
    cudaFuncSetAttribute(attn_mma, cudaFuncAttributeMaxDynamicSharedMemorySize, ASMEM);
    cudaFuncSetAttribute(gemm_mma<0, D,  true,  128>, cudaFuncAttributeMaxDynamicSharedMemorySize, SM128);
    cudaFuncSetAttribute(gemm_mma<2, D,  false, 64 >, cudaFuncAttributeMaxDynamicSharedMemorySize, SM64);
    cudaFuncSetAttribute(gemm_mma<1, D,  true,  128>, cudaFuncAttributeMaxDynamicSharedMemorySize, SM128);
    cudaFuncSetAttribute(gemm_mma<2, FF, false, 64 >, cudaFuncAttributeMaxDynamicSharedMemorySize, SM64);

    // fused weight conversions
    f2bf4_kernel<<<(SZT / 4 + 255) / 256, 256>>>(in_w, wqkv, out_w, wout, w1, w1b, w2, w2b);

    // 1. LN1 -> bf16
    ln_kernel<<<L / 8, 256>>>(x, ln1_g, ln1_b, hbf);
    // 2. QKV projection -> bf16
    gemm_mma<0, D, true, 128><<<dim3(TD / 128, L / 128), 256, SM128>>>(
        hbf, wqkv, in_b, nullptr, nullptr, qkvb, TD);
    // 3. Local-window attention -> bf16
    attn_mma<<<dim3(L / AQT, H), 256, ASMEM>>>(qkvb, obf);
    // 4. Out projection + residual -> fp32 x1 (BM=64: 128 CTAs)
    gemm_mma<2, D, false, 64><<<dim3(D / 128, L / 64), 256, SM64>>>(
        obf, wout, out_b, x, x1, nullptr, D);
    // 5. LN2 -> bf16
    ln_kernel<<<L / 8, 256>>>(x1, ln2_g, ln2_b, h2bf);
    // 6. FFN up + exact GELU -> bf16
    gemm_mma<1, D, true, 128><<<dim3(FF / 128, L / 128), 256, SM128>>>(
        h2bf, w1b, b1, nullptr, nullptr, f1bf, FF);
    // 7. FFN down + residual -> final output (BM=64: 128 CTAs)
    gemm_mma<2, FF, false, 64><<<dim3(D / 128, L / 64), 256, SM64>>>(
        f1bf, w2b, b2, x1, out, nullptr, D);
}